// round 1
// baseline (speedup 1.0000x reference)
#include <cuda_runtime.h>

typedef unsigned long long u64;

#define NB 16
#define NT 96
#define NN 325
#define ND 64
#define NH 64
#define NROWS (NB*NN)          // 5200
#define BTN (NB*NT*NN)         // 499200
#define HSTRIDE (NN*NH)        // 20800 (per t)
#define BSTRIDE (NT*NN*NH)     // 1996800 (per b)

// Scratch: precomputed input projections, laid out [t][row][cols] with row = b*NN+n
__device__ float g_A[(size_t)BTN * 256];   // x@U_x + b_x  (f,i,o,u pre-activations)
__device__ float g_G[(size_t)BTN * 128];   // o_s@U_g + b_g (gov pre-activations)

// ---------- packed fp32x2 helpers (Blackwell FFMA2 path) ----------
__device__ __forceinline__ u64 pack2(float v){
    u64 d; unsigned int b = __float_as_uint(v);
    asm("mov.b64 %0, {%1, %1};" : "=l"(d) : "r"(b));
    return d;
}
__device__ __forceinline__ u64 ffma2(u64 a, u64 b, u64 c){
    u64 d; asm("fma.rn.f32x2 %0, %1, %2, %3;" : "=l"(d) : "l"(a), "l"(b), "l"(c));
    return d;
}
__device__ __forceinline__ u64 fadd2(u64 a, u64 b){
    u64 d; asm("add.rn.f32x2 %0, %1, %2;" : "=l"(d) : "l"(a), "l"(b));
    return d;
}
__device__ __forceinline__ float sigf(float x){
    return __fdividef(1.0f, 1.0f + __expf(-x));
}
__device__ __forceinline__ float tanhf_fast(float x){
    return __fdividef(2.0f, 1.0f + __expf(-2.0f*x)) - 1.0f;
}

// =====================================================================
// Phase 1: A = x @ U_x + b_x ; G = o_s @ U_g + b_g
//   combined 384-wide output per row; 192 f32x2 column-pairs
//   64 rows per tile, 256 threads: warp -> 8 rows, lane -> 6 col-pairs
// =====================================================================
#define P1_THREADS 256
#define P1_ROWS 64
#define P1_TILES (BTN / P1_ROWS)   // 7800
#define P1_SMEM (64*192*8 + 192*8 + 2*64*64*8)   // 165376 B

__global__ void __launch_bounds__(P1_THREADS, 1)
glstm_pre(const float* __restrict__ x, const float* __restrict__ osrc,
          const float* __restrict__ Ux, const float* __restrict__ bx,
          const float* __restrict__ Ug, const float* __restrict__ bg)
{
    extern __shared__ unsigned char sraw[];
    u64* Ws    = (u64*)sraw;          // [64][192] weight pairs (Ux | Ug)
    u64* bias2 = Ws + 64*192;         // [192]
    u64* xs2   = bias2 + 192;         // [64][64] duplicated-pair x tile
    u64* os2   = xs2 + 64*64;         // [64][64] duplicated-pair o_s tile

    const int tid = threadIdx.x;
    const u64* Uxu = (const u64*)Ux;
    const u64* Ugu = (const u64*)Ug;
    for (int i = tid; i < 64*192; i += P1_THREADS){
        int k = i / 192, jp = i - k*192;
        Ws[i] = (jp < 128) ? Uxu[k*128 + jp] : Ugu[k*64 + (jp - 128)];
    }
    if (tid < 192)
        bias2[tid] = (tid < 128) ? ((const u64*)bx)[tid] : ((const u64*)bg)[tid - 128];
    __syncthreads();

    const int lane = tid & 31;
    const int warp = tid >> 5;     // 0..7
    u64* Au = (u64*)g_A;
    u64* Gu = (u64*)g_G;

    for (int tile = blockIdx.x; tile < P1_TILES; tile += gridDim.x){
        const long long m0 = (long long)tile * P1_ROWS;
        // stage inputs (contiguous 16KB chunk each), duplicated into pairs
        for (int i = tid; i < P1_ROWS*64; i += P1_THREADS){
            xs2[i] = pack2(x[m0*64 + i]);
            os2[i] = pack2(osrc[m0*64 + i]);
        }
        __syncthreads();

        u64 b6[6];
        #pragma unroll
        for (int p = 0; p < 6; p++) b6[p] = bias2[p*32 + lane];
        u64 acc[8][6];
        #pragma unroll
        for (int r = 0; r < 8; r++)
            #pragma unroll
            for (int p = 0; p < 6; p++) acc[r][p] = b6[p];

        #pragma unroll 4
        for (int k = 0; k < 64; k++){
            u64 hx[8], ho[8];
            #pragma unroll
            for (int r = 0; r < 8; r++){
                int lr = warp*8 + r;
                hx[r] = xs2[lr*64 + k];   // broadcast 8B
                ho[r] = os2[lr*64 + k];
            }
            #pragma unroll
            for (int p = 0; p < 6; p++){
                u64 w = Ws[k*192 + p*32 + lane];
                if (p < 4){
                    #pragma unroll
                    for (int r = 0; r < 8; r++) acc[r][p] = ffma2(hx[r], w, acc[r][p]);
                } else {
                    #pragma unroll
                    for (int r = 0; r < 8; r++) acc[r][p] = ffma2(ho[r], w, acc[r][p]);
                }
            }
        }

        // scatter to [t][row] layout
        #pragma unroll
        for (int r = 0; r < 8; r++){
            long long m = m0 + warp*8 + r;       // m = (b*NT + t)*NN + n
            int q = (int)(m / NN);
            int n = (int)(m - (long long)q * NN);
            int t = q % NT;
            int b = q / NT;
            long long rho = (long long)b*NN + n;
            u64* Ap = Au + ((long long)t*NROWS + rho)*128;
            #pragma unroll
            for (int p = 0; p < 4; p++) Ap[p*32 + lane] = acc[r][p];
            u64* Gp = Gu + ((long long)t*NROWS + rho)*64;
            Gp[lane]      = acc[r][4];
            Gp[32 + lane] = acc[r][5];
        }
        __syncthreads();
    }
}

// =====================================================================
// Phase 2: recurrence. 145 blocks x 36 rows (single wave, no inter-block
// dependency). ht kept in smem as duplicated f32x2; ct in registers.
// Per step: gates = Apre(global, prefetched) + ht@[Vx|Vg] (FFMA2), then
// elementwise sigmoid/tanh update.
// =====================================================================
#define P2_THREADS 256
#define P2_R 36
#define P2_BLOCKS 145                 // 145*36 = 5220 >= 5200
#define P2_SMEM (64*192*8 + 36*64*8 + 36*384*4)   // 172032 B

__global__ void __launch_bounds__(P2_THREADS, 1)
glstm_rec(const float* __restrict__ Vx, const float* __restrict__ Vg,
          float* __restrict__ hidden, float* __restrict__ htp, float* __restrict__ ctp)
{
    extern __shared__ unsigned char sraw[];
    u64*   Ws    = (u64*)sraw;               // [64][192]
    u64*   hts2  = Ws + 64*192;              // [36][64] duplicated pairs
    float* gates = (float*)(hts2 + 36*64);   // [36][384]
    u64*   gatesu = (u64*)gates;

    const int tid  = threadIdx.x;
    const int lane = tid & 31;
    const int warp = tid >> 5;   // 0..7
    const int blk  = blockIdx.x;

    const u64* Vxu = (const u64*)Vx;
    const u64* Vgu = (const u64*)Vg;
    for (int i = tid; i < 64*192; i += P2_THREADS){
        int k = i / 192, jp = i - k*192;
        Ws[i] = (jp < 128) ? Vxu[k*128 + jp] : Vgu[k*64 + (jp - 128)];
    }
    for (int i = tid; i < 36*64; i += P2_THREADS) hts2[i] = 0ull;

    // each thread owns 9 (row,h) state elements across all steps
    float creg[9];
    int   hbase[9], fbase[9];
    bool  evalid[9];
    #pragma unroll
    for (int j = 0; j < 9; j++){
        int e = tid + j*P2_THREADS;      // 0..2303
        int r = e >> 6, h = e & 63;
        int rho = blk*P2_R + r;
        evalid[j] = (rho < NROWS);
        creg[j] = 0.0f;
        int rr = evalid[j] ? rho : 0;
        int b = rr / NN, n = rr - b*NN;
        hbase[j] = b*BSTRIDE + n*NH + h;
        fbase[j] = rr*NH + h;
    }

    // matmul rows for this warp: r = warp + 8*j
    const int nr = (warp < 4) ? 5 : 4;   // warps 0-3 also cover rows 32..35
    __syncthreads();

    for (int t = 0; t < NT; t++){
        // prefetch input-projection pre-activations (consumed after k-loop)
        u64 apre[5][6];
        #pragma unroll
        for (int j = 0; j < 5; j++){
            if (j < nr){
                long long rho = (long long)blk*P2_R + (warp + 8*j);
                if (rho < NROWS){
                    const u64* Ap = (const u64*)g_A + ((long long)t*NROWS + rho)*128;
                    const u64* Gp = (const u64*)g_G + ((long long)t*NROWS + rho)*64;
                    #pragma unroll
                    for (int p = 0; p < 4; p++) apre[j][p] = Ap[p*32 + lane];
                    apre[j][4] = Gp[lane];
                    apre[j][5] = Gp[32 + lane];
                } else {
                    #pragma unroll
                    for (int p = 0; p < 6; p++) apre[j][p] = 0ull;
                }
            }
        }

        u64 acc[5][6];
        #pragma unroll
        for (int j = 0; j < 5; j++)
            #pragma unroll
            for (int p = 0; p < 6; p++) acc[j][p] = 0ull;

        #pragma unroll 4
        for (int k = 0; k < 64; k++){
            u64 hb[5];
            #pragma unroll
            for (int j = 0; j < 5; j++)
                if (j < nr) hb[j] = hts2[(warp + 8*j)*64 + k];   // broadcast
            #pragma unroll
            for (int p = 0; p < 6; p++){
                u64 w = Ws[k*192 + p*32 + lane];
                #pragma unroll
                for (int j = 0; j < 5; j++)
                    if (j < nr) acc[j][p] = ffma2(hb[j], w, acc[j][p]);
            }
        }

        #pragma unroll
        for (int j = 0; j < 5; j++){
            if (j < nr){
                int r = warp + 8*j;
                #pragma unroll
                for (int p = 0; p < 6; p++)
                    gatesu[r*192 + p*32 + lane] = fadd2(acc[j][p], apre[j][p]);
            }
        }
        __syncthreads();

        // elementwise LSTM update
        #pragma unroll
        for (int j = 0; j < 9; j++){
            int e = tid + j*P2_THREADS;
            int r = e >> 6, h = e & 63;
            const float* g = gates + r*384;
            float ft = sigf(g[h]);
            float it = sigf(g[64  + h]);
            float ot = sigf(g[128 + h]);
            float ut = sigf(g[192 + h]);
            float gf = sigf(g[256 + h]);
            float gu = sigf(g[320 + h]);
            float c  = gf*ft*creg[j] + gu*it*ut;
            creg[j]  = c;
            float hn = ot * tanhf_fast(c);
            hts2[e] = pack2(hn);
            if (evalid[j]){
                hidden[hbase[j] + t*HSTRIDE] = hn;
                if (t == NT-1){
                    htp[fbase[j]] = hn;
                    ctp[fbase[j]] = c;
                }
            }
        }
        __syncthreads();
    }
}

extern "C" void kernel_launch(void* const* d_in, const int* in_sizes, int n_in,
                              void* d_out, int out_size)
{
    const float* x   = (const float*)d_in[0];
    const float* o_s = (const float*)d_in[1];
    const float* Ux  = (const float*)d_in[2];
    const float* Vx  = (const float*)d_in[3];
    const float* bx  = (const float*)d_in[4];
    const float* Ug  = (const float*)d_in[5];
    const float* Vg  = (const float*)d_in[6];
    const float* bg  = (const float*)d_in[7];

    float* out    = (float*)d_out;
    float* hidden = out;                               // [B,T,N,H]
    float* htp    = out + (size_t)BTN * NH;            // [B,N,H]
    float* ctp    = htp + (size_t)NROWS * NH;          // [B,N,H]

    cudaFuncSetAttribute(glstm_pre, cudaFuncAttributeMaxDynamicSharedMemorySize, P1_SMEM);
    cudaFuncSetAttribute(glstm_rec, cudaFuncAttributeMaxDynamicSharedMemorySize, P2_SMEM);

    glstm_pre<<<152, P1_THREADS, P1_SMEM>>>(x, o_s, Ux, bx, Ug, bg);
    glstm_rec<<<P2_BLOCKS, P2_THREADS, P2_SMEM>>>(Vx, Vg, hidden, htp, ctp);
}

// round 2
// speedup vs baseline: 1.0660x; 1.0660x over previous
#include <cuda_runtime.h>

typedef unsigned long long u64;

#define NB 16
#define NT 96
#define NN 325
#define ND 64
#define NH 64
#define NROWS (NB*NN)          // 5200
#define BTN (NB*NT*NN)         // 499200
#define HSTRIDE (NN*NH)        // 20800 (per t)
#define BSTRIDE (NT*NN*NH)     // 1996800 (per b)

// Scratch: precomputed input projections, laid out [t][row][cols], row = b*NN+n
__device__ float g_A[(size_t)BTN * 256];   // x@U_x + b_x
__device__ float g_G[(size_t)BTN * 128];   // o_s@U_g + b_g

// ---------- packed fp32x2 helpers ----------
__device__ __forceinline__ u64 pack2(float v){
    u64 d; unsigned int b = __float_as_uint(v);
    asm("mov.b64 %0, {%1, %1};" : "=l"(d) : "r"(b));
    return d;
}
__device__ __forceinline__ u64 ffma2(u64 a, u64 b, u64 c){
    u64 d; asm("fma.rn.f32x2 %0, %1, %2, %3;" : "=l"(d) : "l"(a), "l"(b), "l"(c));
    return d;
}
__device__ __forceinline__ u64 fadd2(u64 a, u64 b){
    u64 d; asm("add.rn.f32x2 %0, %1, %2;" : "=l"(d) : "l"(a), "l"(b));
    return d;
}
__device__ __forceinline__ float lo32(u64 v){ return __uint_as_float((unsigned)v); }
__device__ __forceinline__ float hi32(u64 v){ return __uint_as_float((unsigned)(v >> 32)); }

// =====================================================================
// Phase 1: A = x @ U_x + b_x ; G = o_s @ U_g + b_g
// 64-row tiles, 256 threads; warp -> 8 rows, lane -> 6 col-pairs.
// 16B k-pair broadcasts + interleaved weights -> fma-bound.
// =====================================================================
#define P1_THREADS 256
#define P1_ROWS 64
#define P1_TILES (BTN / P1_ROWS)   // 7800
#define P1_GRID 148
#define P1_SMEM (64*192*8 + 192*8 + 2*64*64*8)   // 165376 B

__global__ void __launch_bounds__(P1_THREADS, 1)
glstm_pre(const float* __restrict__ x, const float* __restrict__ osrc,
          const float* __restrict__ Ux, const float* __restrict__ bx,
          const float* __restrict__ Ug, const float* __restrict__ bg)
{
    extern __shared__ unsigned char sraw[];
    u64* Wsi   = (u64*)sraw;          // [32][192][2] interleaved (k even/odd)
    u64* bias2 = Wsi + 64*192;        // [192]
    u64* xs2   = bias2 + 192;         // [64][64] duplicated pairs
    u64* os2   = xs2 + 64*64;

    const int tid = threadIdx.x;
    const u64* Uxu = (const u64*)Ux;
    const u64* Ugu = (const u64*)Ug;
    for (int i = tid; i < 64*192; i += P1_THREADS){
        int k = i / 192, jp = i - k*192;
        u64 v = (jp < 128) ? Uxu[k*128 + jp] : Ugu[k*64 + (jp - 128)];
        Wsi[(k >> 1)*384 + jp*2 + (k & 1)] = v;
    }
    if (tid < 192)
        bias2[tid] = (tid < 128) ? ((const u64*)bx)[tid] : ((const u64*)bg)[tid - 128];
    __syncthreads();

    const int lane = tid & 31;
    const int warp = tid >> 5;     // 0..7
    u64* Au = (u64*)g_A;
    u64* Gu = (u64*)g_G;

    for (int tile = blockIdx.x; tile < P1_TILES; tile += gridDim.x){
        const long long m0 = (long long)tile * P1_ROWS;
        for (int i = tid; i < P1_ROWS*64; i += P1_THREADS){
            xs2[i] = pack2(x[m0*64 + i]);
            os2[i] = pack2(osrc[m0*64 + i]);
        }
        __syncthreads();

        u64 acc[8][6];
        #pragma unroll
        for (int r = 0; r < 8; r++){
            #pragma unroll
            for (int p = 0; p < 6; p++) acc[r][p] = bias2[p*32 + lane];
        }

        #pragma unroll 4
        for (int k = 0; k < 64; k += 2){
            ulonglong2 hx[8], ho[8];
            #pragma unroll
            for (int r = 0; r < 8; r++){
                int lr = warp*8 + r;
                hx[r] = *(const ulonglong2*)&xs2[lr*64 + k];   // 16B broadcast
                ho[r] = *(const ulonglong2*)&os2[lr*64 + k];
            }
            #pragma unroll
            for (int p = 0; p < 6; p++){
                ulonglong2 w = *(const ulonglong2*)&Wsi[(k >> 1)*384 + (p*32 + lane)*2];
                if (p < 4){
                    #pragma unroll
                    for (int r = 0; r < 8; r++){
                        acc[r][p] = ffma2(hx[r].x, w.x, acc[r][p]);
                        acc[r][p] = ffma2(hx[r].y, w.y, acc[r][p]);
                    }
                } else {
                    #pragma unroll
                    for (int r = 0; r < 8; r++){
                        acc[r][p] = ffma2(ho[r].x, w.x, acc[r][p]);
                        acc[r][p] = ffma2(ho[r].y, w.y, acc[r][p]);
                    }
                }
            }
        }

        // scatter to [t][row] layout
        #pragma unroll
        for (int r = 0; r < 8; r++){
            long long m = m0 + warp*8 + r;       // m = (b*NT + t)*NN + n
            int q = (int)(m / NN);
            int n = (int)(m - (long long)q * NN);
            int t = q % NT;
            int b = q / NT;
            long long rho = (long long)b*NN + n;
            u64* Ap = Au + ((long long)t*NROWS + rho)*128;
            #pragma unroll
            for (int p = 0; p < 4; p++) Ap[p*32 + lane] = acc[r][p];
            u64* Gp = Gu + ((long long)t*NROWS + rho)*64;
            Gp[lane]      = acc[r][4];
            Gp[32 + lane] = acc[r][5];
        }
        __syncthreads();
    }
}

// =====================================================================
// Phase 2: recurrence. 130 blocks x 40 rows (exact, single wave).
// 8 warps x 5 rows x 6 col-pairs; in-register elementwise (thread's
// acc pairs are the 6 gates at h = 2*lane, 2*lane+1).
// =====================================================================
#define P2_THREADS 256
#define P2_R 40
#define P2_BLOCKS 130                 // 130*40 = 5200 exact
#define P2_SMEM (64*192*8 + P2_R*64*8)   // 118784 B

__global__ void __launch_bounds__(P2_THREADS, 1)
glstm_rec(const float* __restrict__ Vx, const float* __restrict__ Vg,
          float* __restrict__ hidden, float* __restrict__ htp, float* __restrict__ ctp)
{
    extern __shared__ unsigned char sraw[];
    u64* Wsi  = (u64*)sraw;               // [32][192][2] interleaved
    u64* hts2 = Wsi + 64*192;             // [40][64] duplicated pairs

    const int tid  = threadIdx.x;
    const int lane = tid & 31;
    const int warp = tid >> 5;   // 0..7
    const int blk  = blockIdx.x;

    const u64* Vxu = (const u64*)Vx;
    const u64* Vgu = (const u64*)Vg;
    for (int i = tid; i < 64*192; i += P2_THREADS){
        int k = i / 192, jp = i - k*192;
        u64 v = (jp < 128) ? Vxu[k*128 + jp] : Vgu[k*64 + (jp - 128)];
        Wsi[(k >> 1)*384 + jp*2 + (k & 1)] = v;
    }
    for (int i = tid; i < P2_R*64; i += P2_THREADS) hts2[i] = 0ull;

    // this thread owns rows r = warp + 8j (j=0..4), h = 2*lane, 2*lane+1
    float c0[5], c1[5];
    int   gbase[5];     // b*BSTRIDE + n*64 + 2*lane
    int   fbase[5];     // rho*64 + 2*lane
    #pragma unroll
    for (int j = 0; j < 5; j++){
        c0[j] = 0.0f; c1[j] = 0.0f;
        int rho = blk*P2_R + warp + 8*j;     // < 5200 always
        int b = rho / NN, n = rho - b*NN;
        gbase[j] = b*BSTRIDE + n*NH + 2*lane;
        fbase[j] = rho*NH + 2*lane;
    }
    __syncthreads();

    for (int t = 0; t < NT; t++){
        // prefetch input-projection pre-activations (consumed after k-loop)
        u64 apre[5][6];
        #pragma unroll
        for (int j = 0; j < 5; j++){
            long long rho = (long long)blk*P2_R + (warp + 8*j);
            const u64* Ap = (const u64*)g_A + ((long long)t*NROWS + rho)*128;
            const u64* Gp = (const u64*)g_G + ((long long)t*NROWS + rho)*64;
            #pragma unroll
            for (int p = 0; p < 4; p++) apre[j][p] = Ap[p*32 + lane];
            apre[j][4] = Gp[lane];
            apre[j][5] = Gp[32 + lane];
        }

        u64 acc[5][6];
        #pragma unroll
        for (int j = 0; j < 5; j++)
            #pragma unroll
            for (int p = 0; p < 6; p++) acc[j][p] = 0ull;

        #pragma unroll 4
        for (int k = 0; k < 64; k += 2){
            ulonglong2 hb[5];
            #pragma unroll
            for (int j = 0; j < 5; j++)
                hb[j] = *(const ulonglong2*)&hts2[(warp + 8*j)*64 + k];  // 16B broadcast
            #pragma unroll
            for (int p = 0; p < 6; p++){
                ulonglong2 w = *(const ulonglong2*)&Wsi[(k >> 1)*384 + (p*32 + lane)*2];
                #pragma unroll
                for (int j = 0; j < 5; j++){
                    acc[j][p] = ffma2(hb[j].x, w.x, acc[j][p]);
                    acc[j][p] = ffma2(hb[j].y, w.y, acc[j][p]);
                }
            }
        }
        __syncthreads();   // all reads of hts2 done

        // in-register elementwise: gates p at h=2*lane (lo) and 2*lane+1 (hi)
        #pragma unroll
        for (int j = 0; j < 5; j++){
            u64 gp[6];
            #pragma unroll
            for (int p = 0; p < 6; p++) gp[p] = fadd2(acc[j][p], apre[j][p]);

            float hn0, hn1;
            {   // h = 2*lane
                float ef = __expf(-lo32(gp[0]));
                float eg = __expf(-lo32(gp[4]));
                float fgf = __fdividef(1.0f, 1.0f + ef + eg + ef*eg);      // ft*gf
                float ei = __expf(-lo32(gp[1]));
                float eu = __expf(-lo32(gp[3]));
                float ev = __expf(-lo32(gp[5]));
                float iuu = __fdividef(1.0f, (1.0f+ei)*(1.0f+eu)*(1.0f+ev)); // it*ut*gu
                float c = fgf*c0[j] + iuu;
                c0[j] = c;
                float ot = __fdividef(1.0f, 1.0f + __expf(-lo32(gp[2])));
                float th = 1.0f - __fdividef(2.0f, 1.0f + __expf(2.0f*c));
                hn0 = ot * th;
            }
            {   // h = 2*lane+1
                float ef = __expf(-hi32(gp[0]));
                float eg = __expf(-hi32(gp[4]));
                float fgf = __fdividef(1.0f, 1.0f + ef + eg + ef*eg);
                float ei = __expf(-hi32(gp[1]));
                float eu = __expf(-hi32(gp[3]));
                float ev = __expf(-hi32(gp[5]));
                float iuu = __fdividef(1.0f, (1.0f+ei)*(1.0f+eu)*(1.0f+ev));
                float c = fgf*c1[j] + iuu;
                c1[j] = c;
                float ot = __fdividef(1.0f, 1.0f + __expf(-hi32(gp[2])));
                float th = 1.0f - __fdividef(2.0f, 1.0f + __expf(2.0f*c));
                hn1 = ot * th;
            }

            int r = warp + 8*j;
            ulonglong2 hw; hw.x = pack2(hn0); hw.y = pack2(hn1);
            *(ulonglong2*)&hts2[r*64 + 2*lane] = hw;             // STS.128

            float2 hv = make_float2(hn0, hn1);
            *(float2*)&hidden[gbase[j] + t*HSTRIDE] = hv;
            if (t == NT-1){
                *(float2*)&htp[fbase[j]] = hv;
                *(float2*)&ctp[fbase[j]] = make_float2(c0[j], c1[j]);
            }
        }
        __syncthreads();   // hts2 writes visible before next step
    }
}

extern "C" void kernel_launch(void* const* d_in, const int* in_sizes, int n_in,
                              void* d_out, int out_size)
{
    const float* x   = (const float*)d_in[0];
    const float* o_s = (const float*)d_in[1];
    const float* Ux  = (const float*)d_in[2];
    const float* Vx  = (const float*)d_in[3];
    const float* bx  = (const float*)d_in[4];
    const float* Ug  = (const float*)d_in[5];
    const float* Vg  = (const float*)d_in[6];
    const float* bg  = (const float*)d_in[7];

    float* out    = (float*)d_out;
    float* hidden = out;                               // [B,T,N,H]
    float* htp    = out + (size_t)BTN * NH;            // [B,N,H]
    float* ctp    = htp + (size_t)NROWS * NH;          // [B,N,H]

    cudaFuncSetAttribute(glstm_pre, cudaFuncAttributeMaxDynamicSharedMemorySize, P1_SMEM);
    cudaFuncSetAttribute(glstm_rec, cudaFuncAttributeMaxDynamicSharedMemorySize, P2_SMEM);

    glstm_pre<<<P1_GRID, P1_THREADS, P1_SMEM>>>(x, o_s, Ux, bx, Ug, bg);
    glstm_rec<<<P2_BLOCKS, P2_THREADS, P2_SMEM>>>(Vx, Vg, hidden, htp, ctp);
}

// round 4
// speedup vs baseline: 1.4594x; 1.3690x over previous
#include <cuda_runtime.h>
#include <cuda_bf16.h>
#include <cstdint>

typedef unsigned long long u64;
typedef unsigned int u32;

#define NB 16
#define NT 96
#define NN 325
#define ND 64
#define NH 64
#define NROWS (NB*NN)          // 5200
#define BTN (NB*NT*NN)         // 499200
#define HSTRIDE (NN*NH)        // 20800
#define BSTRIDE (NT*NN*NH)     // 1996800

// Scratch: precomputed input projections, [t][row][cols], row = b*NN+n
__device__ float g_A[(size_t)BTN * 256];   // x@U_x + b_x
__device__ float g_G[(size_t)BTN * 128];   // o_s@U_g + b_g

// ================= helpers =================
__device__ __forceinline__ u32 smem_u32(const void* p){
    u32 a; asm("{ .reg .u64 t; cvta.to.shared.u64 t, %1; cvt.u32.u64 %0, t; }" : "=r"(a) : "l"(p));
    return a;
}
// pack two floats to bf16x2: lo_elem -> low 16 bits, hi_elem -> high 16 bits
__device__ __forceinline__ u32 bfpack(float lo_elem, float hi_elem){
    u32 r; asm("cvt.rn.bf16x2.f32 %0, %1, %2;" : "=r"(r) : "f"(hi_elem), "f"(lo_elem));
    return r;
}
__device__ __forceinline__ void ldsm_x4(u32& a0,u32& a1,u32& a2,u32& a3, u32 addr){
    asm volatile("ldmatrix.sync.aligned.m8n8.x4.shared.b16 {%0,%1,%2,%3}, [%4];"
      : "=r"(a0),"=r"(a1),"=r"(a2),"=r"(a3) : "r"(addr));
}
__device__ __forceinline__ void ldsm_x2(u32& b0,u32& b1, u32 addr){
    asm volatile("ldmatrix.sync.aligned.m8n8.x2.shared.b16 {%0,%1}, [%2];"
      : "=r"(b0),"=r"(b1) : "r"(addr));
}
__device__ __forceinline__ void mma16816(float* c, const u32* a, const u32* b){
    asm volatile("mma.sync.aligned.m16n8k16.row.col.f32.bf16.bf16.f32 "
      "{%0,%1,%2,%3}, {%4,%5,%6,%7}, {%8,%9}, {%0,%1,%2,%3};"
      : "+f"(c[0]),"+f"(c[1]),"+f"(c[2]),"+f"(c[3])
      : "r"(a[0]),"r"(a[1]),"r"(a[2]),"r"(a[3]), "r"(b[0]),"r"(b[1]));
}

// ---------- packed fp32x2 (phase 2) ----------
__device__ __forceinline__ u64 pack2(float v){
    u64 d; unsigned int b = __float_as_uint(v);
    asm("mov.b64 %0, {%1, %1};" : "=l"(d) : "r"(b));
    return d;
}
__device__ __forceinline__ u64 ffma2(u64 a, u64 b, u64 c){
    u64 d; asm("fma.rn.f32x2 %0, %1, %2, %3;" : "=l"(d) : "l"(a), "l"(b), "l"(c));
    return d;
}
__device__ __forceinline__ u64 fadd2(u64 a, u64 b){
    u64 d; asm("add.rn.f32x2 %0, %1, %2;" : "=l"(d) : "l"(a), "l"(b));
    return d;
}
__device__ __forceinline__ float lo32(u64 v){ return __uint_as_float((unsigned)v); }
__device__ __forceinline__ float hi32(u64 v){ return __uint_as_float((unsigned)(v >> 32)); }

// =====================================================================
// Phase 1 (HMMA): per 64-row tile compute fused [xUx+bx | oUg+bg] (N=384)
// via split-3 bf16: A'=[hi|hi|lo] (K'=192), B'=[Whi;Wlo;Whi].
// smem rows padded to 400B for conflict-free ldmatrix.
// =====================================================================
#define P1_THREADS 256
#define P1_ROWS 64
#define P1_TILES (BTN/P1_ROWS)   // 7800
#define P1_GRID 148

#define PITCH 400                // bytes per logical row (192 bf16 + pad)
#define S_BIAS 0                 // 384 f32 = 1536
#define S_B    1536              // 384 * 400 = 153600
#define S_AX   155136            // 64 * 400 = 25600
#define S_AO   180736            // 64 * 400 = 25600
#define P1_SMEM 206336

__global__ void __launch_bounds__(P1_THREADS, 1)
glstm_pre_mma(const float* __restrict__ x, const float* __restrict__ osrc,
              const float* __restrict__ Ux, const float* __restrict__ bx,
              const float* __restrict__ Ug, const float* __restrict__ bg)
{
    extern __shared__ unsigned char smem[];
    float* bias_s = (float*)(smem + S_BIAS);
    const int tid = threadIdx.x;
    const int w   = tid >> 5;         // warp 0..7
    const int lane = tid & 31;
    const int gid = lane >> 2, tid4 = lane & 3;

    // ---- bias ----
    bias_s[tid] = bx[tid];
    if (tid < 128) bias_s[256 + tid] = bg[tid];

    // ---- build B': row n (0..383), cols k'=0..191 : [Whi | Wlo | Whi] ----
    for (int i = tid; i < 64*256; i += P1_THREADS){    // Ux part
        int n = i & 255, k = i >> 8;
        float v = Ux[k*256 + n];
        __nv_bfloat16 hb = __float2bfloat16(v);
        float lo = v - __bfloat162float(hb);
        __nv_bfloat16* row = (__nv_bfloat16*)(smem + S_B + n*PITCH);
        row[k] = hb; row[128 + k] = hb;
        row[64 + k] = __float2bfloat16(lo);
    }
    for (int i = tid; i < 64*128; i += P1_THREADS){    // Ug part
        int n = i & 127, k = i >> 7;
        float v = Ug[k*128 + n];
        __nv_bfloat16 hb = __float2bfloat16(v);
        float lo = v - __bfloat162float(hb);
        __nv_bfloat16* row = (__nv_bfloat16*)(smem + S_B + (256 + n)*PITCH);
        row[k] = hb; row[128 + k] = hb;
        row[64 + k] = __float2bfloat16(lo);
    }

    const u32 sb = smem_u32(smem);
    // ldmatrix base addresses (per-lane)
    u32 rowAx[4], rowAo[4];
    #pragma unroll
    for (int mi = 0; mi < 4; mi++){
        u32 off = (u32)(16*mi + (lane & 15))*PITCH + ((lane >> 4) << 4);
        rowAx[mi] = sb + S_AX + off;
        rowAo[mi] = sb + S_AO + off;
    }
    u32 rowB[6];
    #pragma unroll
    for (int ni = 0; ni < 6; ni++)
        rowB[ni] = sb + S_B + (u32)(48*w + 8*ni + (lane & 7))*PITCH + (((lane >> 3) & 1) << 4);

    const bool needx = (w <= 5), needo = (w >= 5);

    // conversion mapping: thread -> row r, k-quarter q
    const int cr = tid >> 2, ck0 = (tid & 3) << 4;
    u32* ax32 = (u32*)(smem + S_AX + cr*PITCH);
    u32* ao32 = (u32*)(smem + S_AO + cr*PITCH);

    for (int tile = blockIdx.x; tile < P1_TILES; tile += gridDim.x){
        const long long m0 = (long long)tile * P1_ROWS;

        // ---- load + split x,o into A' ----
        {
            const float4* xp = (const float4*)(x    + (size_t)(m0 + cr)*64 + ck0);
            const float4* op = (const float4*)(osrc + (size_t)(m0 + cr)*64 + ck0);
            float4 xv[4], ov[4];
            #pragma unroll
            for (int j = 0; j < 4; j++){ xv[j] = xp[j]; ov[j] = op[j]; }
            #pragma unroll
            for (int j = 0; j < 4; j++){
                #pragma unroll
                for (int h = 0; h < 2; h++){
                    float a = h ? xv[j].z : xv[j].x;
                    float b = h ? xv[j].w : xv[j].y;
                    int k = ck0 + 4*j + 2*h;
                    u32 hp = bfpack(a, b);
                    float ra = a - __uint_as_float(hp << 16);
                    float rb = b - __uint_as_float(hp & 0xFFFF0000u);
                    u32 lp = bfpack(ra, rb);
                    ax32[k>>1] = hp; ax32[32 + (k>>1)] = hp; ax32[64 + (k>>1)] = lp;

                    a = h ? ov[j].z : ov[j].x;
                    b = h ? ov[j].w : ov[j].y;
                    hp = bfpack(a, b);
                    ra = a - __uint_as_float(hp << 16);
                    rb = b - __uint_as_float(hp & 0xFFFF0000u);
                    lp = bfpack(ra, rb);
                    ao32[k>>1] = hp; ao32[32 + (k>>1)] = hp; ao32[64 + (k>>1)] = lp;
                }
            }
        }
        __syncthreads();

        // ---- MMA: 64 x 48 slice per warp, K'=192 ----
        float acc[4][6][4];
        #pragma unroll
        for (int mi = 0; mi < 4; mi++)
            #pragma unroll
            for (int ni = 0; ni < 6; ni++)
                #pragma unroll
                for (int e = 0; e < 4; e++) acc[mi][ni][e] = 0.0f;

        #pragma unroll
        for (int kf = 0; kf < 12; kf++){
            u32 Axf[4][4], Aof[4][4];
            if (needx){
                #pragma unroll
                for (int mi = 0; mi < 4; mi++)
                    ldsm_x4(Axf[mi][0],Axf[mi][1],Axf[mi][2],Axf[mi][3], rowAx[mi] + kf*32);
            }
            if (needo){
                #pragma unroll
                for (int mi = 0; mi < 4; mi++)
                    ldsm_x4(Aof[mi][0],Aof[mi][1],Aof[mi][2],Aof[mi][3], rowAo[mi] + kf*32);
            }
            u32 Bf[6][2];
            #pragma unroll
            for (int ni = 0; ni < 6; ni++)
                ldsm_x2(Bf[ni][0], Bf[ni][1], rowB[ni] + kf*32);

            #pragma unroll
            for (int ni = 0; ni < 6; ni++){
                const bool isx = (48*w + 8*ni) < 256;
                #pragma unroll
                for (int mi = 0; mi < 4; mi++)
                    mma16816(acc[mi][ni], isx ? Axf[mi] : Aof[mi], Bf[ni]);
            }
        }
        __syncthreads();   // all ldmatrix done; A' reusable next tile

        // ---- epilogue: bias + scatter to [t][row] scratch ----
        #pragma unroll
        for (int mi = 0; mi < 4; mi++){
            #pragma unroll
            for (int half = 0; half < 2; half++){
                int r = 16*mi + gid + 8*half;
                long long m = m0 + r;
                u32 mu = (u32)m;
                u32 qq = mu / NN;
                u32 n  = mu - qq*NN;
                u32 t  = qq % NT, b = qq / NT;
                size_t ro = (size_t)t*NROWS + (size_t)b*NN + n;
                float* pA = g_A + ro*256;
                float* pG = g_G + ro*128;
                #pragma unroll
                for (int ni = 0; ni < 6; ni++){
                    int col = 48*w + 8*ni + 2*tid4;
                    float2 bv = *(const float2*)&bias_s[col];
                    float2 cv;
                    cv.x = acc[mi][ni][half*2 + 0] + bv.x;
                    cv.y = acc[mi][ni][half*2 + 1] + bv.y;
                    if (col < 256) *(float2*)(pA + col) = cv;
                    else           *(float2*)(pG + col - 256) = cv;
                }
            }
        }
    }
}

// =====================================================================
// Phase 2: recurrence (FFMA2), ping-pong ht buffers -> ONE barrier/step.
// 130 blocks x 40 rows; 8 warps x 5 rows x 6 col-pairs.
// =====================================================================
#define P2_THREADS 256
#define P2_R 40
#define P2_BLOCKS 130
#define P2_SMEM (64*192*8 + 2*P2_R*64*8)   // 139264 B

__global__ void __launch_bounds__(P2_THREADS, 1)
glstm_rec(const float* __restrict__ Vx, const float* __restrict__ Vg,
          float* __restrict__ hidden, float* __restrict__ htp, float* __restrict__ ctp)
{
    extern __shared__ unsigned char sraw[];
    u64* Wsi  = (u64*)sraw;               // [32][192][2] interleaved
    u64* hbuf = Wsi + 64*192;             // [2][40][64] duplicated pairs

    const int tid  = threadIdx.x;
    const int lane = tid & 31;
    const int warp = tid >> 5;
    const int blk  = blockIdx.x;

    const u64* Vxu = (const u64*)Vx;
    const u64* Vgu = (const u64*)Vg;
    for (int i = tid; i < 64*192; i += P2_THREADS){
        int k = i / 192, jp = i - k*192;
        u64 v = (jp < 128) ? Vxu[k*128 + jp] : Vgu[k*64 + (jp - 128)];
        Wsi[(k >> 1)*384 + jp*2 + (k & 1)] = v;
    }
    for (int i = tid; i < P2_R*64; i += P2_THREADS) hbuf[i] = 0ull;  // buf0 = h(-1)

    float c0[5], c1[5];
    int gbase[5], fbase[5];
    #pragma unroll
    for (int j = 0; j < 5; j++){
        c0[j] = 0.0f; c1[j] = 0.0f;
        int rho = blk*P2_R + warp + 8*j;
        int b = rho / NN, n = rho - b*NN;
        gbase[j] = b*BSTRIDE + n*NH + 2*lane;
        fbase[j] = rho*NH + 2*lane;
    }
    __syncthreads();

    for (int t = 0; t < NT; t++){
        u64* hin  = hbuf + (t & 1)*P2_R*64;
        u64* hout = hbuf + ((t + 1) & 1)*P2_R*64;

        u64 apre[5][6];
        #pragma unroll
        for (int j = 0; j < 5; j++){
            long long rho = (long long)blk*P2_R + (warp + 8*j);
            const u64* Ap = (const u64*)g_A + ((long long)t*NROWS + rho)*128;
            const u64* Gp = (const u64*)g_G + ((long long)t*NROWS + rho)*64;
            #pragma unroll
            for (int p = 0; p < 4; p++) apre[j][p] = Ap[p*32 + lane];
            apre[j][4] = Gp[lane];
            apre[j][5] = Gp[32 + lane];
        }

        u64 acc[5][6];
        #pragma unroll
        for (int j = 0; j < 5; j++)
            #pragma unroll
            for (int p = 0; p < 6; p++) acc[j][p] = 0ull;

        #pragma unroll 4
        for (int k = 0; k < 64; k += 2){
            ulonglong2 hb[5];
            #pragma unroll
            for (int j = 0; j < 5; j++)
                hb[j] = *(const ulonglong2*)&hin[(warp + 8*j)*64 + k];
            #pragma unroll
            for (int p = 0; p < 6; p++){
                ulonglong2 wv = *(const ulonglong2*)&Wsi[(k >> 1)*384 + (p*32 + lane)*2];
                #pragma unroll
                for (int j = 0; j < 5; j++){
                    acc[j][p] = ffma2(hb[j].x, wv.x, acc[j][p]);
                    acc[j][p] = ffma2(hb[j].y, wv.y, acc[j][p]);
                }
            }
        }

        #pragma unroll
        for (int j = 0; j < 5; j++){
            u64 gp[6];
            #pragma unroll
            for (int p = 0; p < 6; p++) gp[p] = fadd2(acc[j][p], apre[j][p]);

            float hn0, hn1;
            {
                float ef = __expf(-lo32(gp[0]));
                float eg = __expf(-lo32(gp[4]));
                float fgf = __fdividef(1.0f, 1.0f + ef + eg + ef*eg);
                float ei = __expf(-lo32(gp[1]));
                float eu = __expf(-lo32(gp[3]));
                float ev = __expf(-lo32(gp[5]));
                float iuu = __fdividef(1.0f, (1.0f+ei)*(1.0f+eu)*(1.0f+ev));
                float c = fgf*c0[j] + iuu;
                c0[j] = c;
                float ot = __fdividef(1.0f, 1.0f + __expf(-lo32(gp[2])));
                float th = 1.0f - __fdividef(2.0f, 1.0f + __expf(2.0f*c));
                hn0 = ot * th;
            }
            {
                float ef = __expf(-hi32(gp[0]));
                float eg = __expf(-hi32(gp[4]));
                float fgf = __fdividef(1.0f, 1.0f + ef + eg + ef*eg);
                float ei = __expf(-hi32(gp[1]));
                float eu = __expf(-hi32(gp[3]));
                float ev = __expf(-hi32(gp[5]));
                float iuu = __fdividef(1.0f, (1.0f+ei)*(1.0f+eu)*(1.0f+ev));
                float c = fgf*c1[j] + iuu;
                c1[j] = c;
                float ot = __fdividef(1.0f, 1.0f + __expf(-hi32(gp[2])));
                float th = 1.0f - __fdividef(2.0f, 1.0f + __expf(2.0f*c));
                hn1 = ot * th;
            }

            int r = warp + 8*j;
            ulonglong2 hw; hw.x = pack2(hn0); hw.y = pack2(hn1);
            *(ulonglong2*)&hout[r*64 + 2*lane] = hw;

            float2 hv = make_float2(hn0, hn1);
            *(float2*)&hidden[gbase[j] + t*HSTRIDE] = hv;
            if (t == NT-1){
                *(float2*)&htp[fbase[j]] = hv;
                *(float2*)&ctp[fbase[j]] = make_float2(c0[j], c1[j]);
            }
        }
        __syncthreads();   // hout(t) visible before step t+1 reads it
    }
}

extern "C" void kernel_launch(void* const* d_in, const int* in_sizes, int n_in,
                              void* d_out, int out_size)
{
    const float* x   = (const float*)d_in[0];
    const float* o_s = (const float*)d_in[1];
    const float* Ux  = (const float*)d_in[2];
    const float* Vx  = (const float*)d_in[3];
    const float* bx  = (const float*)d_in[4];
    const float* Ug  = (const float*)d_in[5];
    const float* Vg  = (const float*)d_in[6];
    const float* bg  = (const float*)d_in[7];

    float* out    = (float*)d_out;
    float* hidden = out;                               // [B,T,N,H]
    float* htp    = out + (size_t)BTN * NH;            // [B,N,H]
    float* ctp    = htp + (size_t)NROWS * NH;          // [B,N,H]

    cudaFuncSetAttribute(glstm_pre_mma, cudaFuncAttributeMaxDynamicSharedMemorySize, P1_SMEM);
    cudaFuncSetAttribute(glstm_rec,     cudaFuncAttributeMaxDynamicSharedMemorySize, P2_SMEM);

    glstm_pre_mma<<<P1_GRID, P1_THREADS, P1_SMEM>>>(x, o_s, Ux, bx, Ug, bg);
    glstm_rec<<<P2_BLOCKS, P2_THREADS, P2_SMEM>>>(Vx, Vg, hidden, htp, ctp);
}